// round 15
// baseline (speedup 1.0000x reference)
#include <cuda_runtime.h>
#include <cstdint>

typedef unsigned long long ull;

__constant__ float cCC[6]  = {0.f, 0.2f, 0.3f, 0.8f, (float)(8.0/9.0), 1.0f};
__constant__ float cBWv[6] = {(float)(35.0/384.0), 0.f, (float)(500.0/1113.0),
                              (float)(125.0/192.0), (float)(-2187.0/6784.0),
                              (float)(11.0/84.0)};

// ---- smem layout (float offsets) ----
#define oXs  0        /* [s:4][128] = 512 */
#define oA   512      /* [s:4][128 local h] = 512 */
#define oPb  1024     /* exchange [p:2][srcrank:4][pr:2][c:128] ull = 4096 floats */
#define oScr 5120     /* 48: trace 32 + dot 16 */
#define oTx  5168     /* 4 */
#define oLp  5172     /* 4 */
#define SMF  5176

__device__ __forceinline__ ull pk(float w) {
  ull r; asm("mov.b64 %0, {%1, %2};" : "=l"(r) : "f"(w), "f"(w)); return r;
}
__device__ __forceinline__ ull mk2(float a, float b) {
  ull r; asm("mov.b64 %0, {%1, %2};" : "=l"(r) : "f"(a), "f"(b)); return r;
}
__device__ __forceinline__ float lo32(ull v) { return __uint_as_float((unsigned)v); }
__device__ __forceinline__ float hi32(ull v) { return __uint_as_float((unsigned)(v >> 32)); }
__device__ __forceinline__ ull f2fma(ull a, ull b, ull c) {
  ull d; asm("fma.rn.f32x2 %0,%1,%2,%3;" : "=l"(d) : "l"(a), "l"(b), "l"(c)); return d;
}
__device__ __forceinline__ ull f2add(ull a, ull b) {
  ull d; asm("add.rn.f32x2 %0,%1,%2;" : "=l"(d) : "l"(a), "l"(b)); return d;
}
__device__ __forceinline__ ull f2mul(ull a, ull b) {
  ull d; asm("mul.rn.f32x2 %0,%1,%2;" : "=l"(d) : "l"(a), "l"(b)); return d;
}
__device__ __forceinline__ float wsum(float v) {
#pragma unroll
  for (int o = 16; o > 0; o >>= 1) v += __shfl_xor_sync(0xffffffffu, v, o);
  return v;
}
__device__ __forceinline__ uint32_t smem_u32(const void* p) {
  uint32_t a;
  asm("{.reg .u64 t; cvta.to.shared.u64 t, %1; cvt.u32.u64 %0, t;}" : "=r"(a) : "l"(p));
  return a;
}
__device__ __forceinline__ uint32_t mapa_u32(uint32_t addr, uint32_t rank) {
  uint32_t ra; asm("mapa.shared::cluster.u32 %0, %1, %2;" : "=r"(ra) : "r"(addr), "r"(rank));
  return ra;
}
__device__ __forceinline__ float ldcf(uint32_t addr, uint32_t rank) {
  uint32_t ra = mapa_u32(addr, rank);
  float v; asm volatile("ld.shared::cluster.f32 %0, [%1];" : "=f"(v) : "r"(ra)); return v;
}
__device__ __forceinline__ void csync() {
  asm volatile("barrier.cluster.arrive.aligned;" ::: "memory");
  asm volatile("barrier.cluster.wait.aligned;" ::: "memory");
}
__device__ __forceinline__ void mbar_init(uint32_t mb, unsigned cnt) {
  asm volatile("mbarrier.init.shared::cta.b64 [%0], %1;" :: "r"(mb), "r"(cnt) : "memory");
}
__device__ __forceinline__ void mbar_arm(uint32_t mb, unsigned tx) {
  asm volatile("mbarrier.arrive.expect_tx.shared::cta.b64 _, [%0], %1;"
               :: "r"(mb), "r"(tx) : "memory");
}
__device__ __forceinline__ void st_async64(uint32_t ra, ull v, uint32_t rmb) {
  asm volatile("st.async.shared::cluster.mbarrier::complete_tx::bytes.b64 [%0], %1, [%2];"
               :: "r"(ra), "l"(v), "r"(rmb) : "memory");
}
__device__ __forceinline__ void waitp(uint32_t mb, unsigned ph) {
  unsigned done;
  asm volatile(
      "{\n\t.reg .pred p;\n\t"
      "mbarrier.try_wait.parity.acquire.cta.shared::cta.b64 p, [%1], %2;\n\t"
      "selp.u32 %0,1,0,p;\n\t}"
      : "=r"(done) : "r"(mb), "r"(ph) : "memory");
  while (!done) {
    asm volatile(
        "{\n\t.reg .pred p;\n\t"
        "mbarrier.try_wait.parity.acquire.cta.shared::cta.b64 p, [%1], %2, 0x989680;\n\t"
        "selp.u32 %0,1,0,p;\n\t}"
        : "=r"(done) : "r"(mb), "r"(ph) : "memory");
  }
}
__device__ __forceinline__ float ftanh(float x) {
  float e = __expf(2.f * x);
  return 1.f - __fdividef(2.f, e + 1.f);
}

__global__ void __launch_bounds__(256, 1) __cluster_dims__(4, 1, 1)
vino_kernel(const float* __restrict__ x0g, const float* __restrict__ W1g,
            const float* __restrict__ b1g, const float* __restrict__ u1g,
            const float* __restrict__ W2g, const float* __restrict__ b2g,
            const int* __restrict__ nsp, float* __restrict__ out, int B) {
  __shared__ __align__(16) float sm[SMF];
  __shared__ __align__(8) unsigned long long smbar[2];
  const int t = threadIdx.x;
  const int w = t >> 5, lane = t & 31;
  // G1 mapping: col c1 (local h), k-half kh; shfl partner = lane^1
  const int c1 = (w << 4) + (lane >> 1);
  const int kh = lane & 1;
  // G2/RK mapping: d-col c2, sample pair pr
  const int c2 = t & 127, pr = t >> 7;
  const int s0i = 2 * pr, s1i = 2 * pr + 1;
  uint32_t rank; asm("mov.u32 %0, %%cluster_ctarank;" : "=r"(rank));
  const int hbase = (int)rank << 7;
  const int sb = (blockIdx.x >> 2) << 2;

  // ---- persistent weights ----
  // W1: col hbase+c1, k in [64kh, 64kh+64): 32 k-pair ull
  ull w1p[32];
#pragma unroll
  for (int i = 0; i < 32; ++i) {
    const int k0 = (kh << 6) + 2 * i;
    w1p[i] = mk2(W1g[k0 * 512 + hbase + c1], W1g[(k0 + 1) * 512 + hbase + c1]);
  }
  // W2: col c2, full local h (128): 64 h-pair ull; w2p[i] = h-pair (2i, 2i+1)
  ull w2p[64];
#pragma unroll
  for (int i = 0; i < 64; ++i) {
    const int h0 = hbase + 2 * i;
    w2p[i] = mk2(W2g[h0 * 128 + c2], W2g[(h0 + 1) * 128 + c2]);
  }

  // ---- per-thread constants ----
  const float b1r = b1g[hbase + c1];
  const float u1r = u1g[hbase + c1];
  const ull b2p = pk(b2g[c2]);
  float mr1 = 0.f;
#pragma unroll 4
  for (int i = 0; i < 128; ++i)
    mr1 = fmaf(W1g[i * 512 + hbase + c1], W2g[(hbase + c1) * 128 + i], mr1);

  // ---- state: y holds (s0i, s1i) at d-col c2 ----
  ull y = mk2(x0g[(sb + s0i) * 128 + c2], x0g[(sb + s1i) * 128 + c2]);
  ull xs = y;
  sm[oXs + s0i * 128 + c2] = lo32(xs);
  sm[oXs + s1i * 128 + c2] = hi32(xs);

  // ---- mbarriers + remote push addresses ----
  const uint32_t sbase = smem_u32(sm);
  const uint32_t mb0 = smem_u32(&smbar[0]);
  if (t == 0) {
    mbar_init(mb0, 1); mbar_init(mb0 + 8, 1);
    mbar_arm(mb0, 6144u); mbar_arm(mb0 + 8, 6144u);  // 3 ranks x 256 thr x 8B
  }
  // my slot in rank r's buffer: [p=0][srcrank][pr][c2]
  uint32_t rdat[3], rmb[3];
  {
    const uint32_t loff =
        sbase + (uint32_t)(oPb + 2 * ((((int)rank << 1) + pr) * 128 + c2)) * 4u;
    int j = 0;
#pragma unroll
    for (uint32_t r = 0; r < 4; ++r) {
      if (r != rank) {
        rdat[j] = mapa_u32(loff, r);
        rmb[j]  = mapa_u32(mb0, r);
        ++j;
      }
    }
  }

  // ---- log p(x0) ----
  {
    float q0 = lo32(y), q1 = hi32(y);
    float ss0 = wsum(q0 * q0), ss1 = wsum(q1 * q1);
    if (lane == 0) { sm[oScr + w * 2] = ss0; sm[oScr + w * 2 + 1] = ss1; }
  }
  __syncthreads();
  if (t < 4) {
    const int gg = t >> 1, sp = t & 1;
    float ss = 0.f;
#pragma unroll
    for (int q = 0; q < 4; ++q) ss += sm[oScr + ((4 * gg + q) << 1) + sp];
    sm[oLp + t] = -0.5f * ss - 117.6241322501981f;  // 64*log(2*pi)
  }
  csync();  // arming + smem init visible cluster-wide

  const int ns = *nsp;
  const float dt = 1.0f / (float)ns;
  ull ks0 = 0, ks1 = 0, ks2 = 0, ks3 = 0, ks4 = 0;
  ull tra = 0, trb = 0;     // per-sample traces (s0,s1) / (s2,s3)
  ull acc_dot = 0;
  unsigned par0 = 0, par1 = 0;

  for (int step = 0; step < ns; ++step) {
    const float tstep = (float)step * dt;
#pragma unroll 1
    for (int stage = 0; stage < 6; ++stage) {
      const float coef = dt * cBWv[stage];
      const float tcur = tstep + cCC[stage] * dt;
      const int p = stage & 1;

      __syncthreads();                       // barA: xs visible
      // ---- G1: h[s][c1] over k-half, combine via shfl, tanh, store a ----
      {
        const float* xb = sm + oXs + (kh << 6);
        ull h0a = 0, h1a = 0, h2a = 0, h3a = 0;
#pragma unroll
        for (int i = 0; i < 16; ++i) {
          ulonglong2 x0 = *(const ulonglong2*)(xb + 0 * 128 + (i << 2));
          ulonglong2 x1 = *(const ulonglong2*)(xb + 1 * 128 + (i << 2));
          ulonglong2 x2 = *(const ulonglong2*)(xb + 2 * 128 + (i << 2));
          ulonglong2 x3 = *(const ulonglong2*)(xb + 3 * 128 + (i << 2));
          ull wa = w1p[2 * i], wb = w1p[2 * i + 1];
          h0a = f2fma(wa, x0.x, h0a); h0a = f2fma(wb, x0.y, h0a);
          h1a = f2fma(wa, x1.x, h1a); h1a = f2fma(wb, x1.y, h1a);
          h2a = f2fma(wa, x2.x, h2a); h2a = f2fma(wb, x2.y, h2a);
          h3a = f2fma(wa, x3.x, h3a); h3a = f2fma(wb, x3.y, h3a);
        }
        float h0 = lo32(h0a) + hi32(h0a);
        float h1 = lo32(h1a) + hi32(h1a);
        float h2 = lo32(h2a) + hi32(h2a);
        float h3 = lo32(h3a) + hi32(h3a);
        h0 += __shfl_xor_sync(0xffffffffu, h0, 1);
        h1 += __shfl_xor_sync(0xffffffffu, h1, 1);
        h2 += __shfl_xor_sync(0xffffffffu, h2, 1);
        h3 += __shfl_xor_sync(0xffffffffu, h3, 1);
        const float bias = fmaf(tcur, u1r, b1r);
        float a0 = ftanh(h0 + bias), a1 = ftanh(h1 + bias);
        float a2 = ftanh(h2 + bias), a3 = ftanh(h3 + bias);
        if (!kh) {
          sm[oA + 0 * 128 + c1] = a0;
          sm[oA + 1 * 128 + c1] = a1;
          sm[oA + 2 * 128 + c1] = a2;
          sm[oA + 3 * 128 + c1] = a3;
          tra = f2fma(mk2((1.f - a0 * a0) * mr1, (1.f - a1 * a1) * mr1),
                      pk(coef), tra);
          trb = f2fma(mk2((1.f - a2 * a2) * mr1, (1.f - a3 * a3) * mr1),
                      pk(coef), trb);
        }
      }
      __syncthreads();                       // barB: a visible

      // ---- G2: complete local-H partial for (s0i, s1i) at d-col c2 ----
      // a-block at h-offset 4i pairs with w2p[2i], w2p[2i+1];
      // a-block at h-offset 64+4i pairs with w2p[32+2i], w2p[32+2i+1].
      ull kpart;
      {
        const float* ab = sm + oA + (pr << 8);
        ull ka = 0, kb = 0;
#pragma unroll
        for (int i = 0; i < 16; ++i) {
          ulonglong2 a0 = *(const ulonglong2*)(ab + (i << 2));
          ulonglong2 a1 = *(const ulonglong2*)(ab + 128 + (i << 2));
          ull wa = w2p[2 * i], wb = w2p[2 * i + 1];
          ka = f2fma(wa, a0.x, ka); ka = f2fma(wb, a0.y, ka);
          kb = f2fma(wa, a1.x, kb); kb = f2fma(wb, a1.y, kb);
          ulonglong2 b0 = *(const ulonglong2*)(ab + (i << 2) + 64);
          ulonglong2 b1 = *(const ulonglong2*)(ab + 128 + (i << 2) + 64);
          ull wc = w2p[32 + 2 * i], wd = w2p[32 + 2 * i + 1];
          ka = f2fma(wc, b0.x, ka); ka = f2fma(wd, b0.y, ka);
          kb = f2fma(wc, b1.x, kb); kb = f2fma(wd, b1.y, kb);
        }
        kpart = mk2(lo32(ka) + hi32(ka), lo32(kb) + hi32(kb));
      }
      // push partial straight from registers to 3 remote ranks
      {
        const uint32_t dof = (uint32_t)p << 13;  // p * 2048 floats * 4B
        const uint32_t mof = (uint32_t)p << 3;
        st_async64(rdat[0] + dof, kpart, rmb[0] + mof);
        st_async64(rdat[1] + dof, kpart, rmb[1] + mof);
        st_async64(rdat[2] + dof, kpart, rmb[2] + mof);
      }
      // wait for 6KB from 3 remotes, re-arm
      {
        const uint32_t lmb = mb0 + (p << 3);
        unsigned ph = p ? par1 : par0;
        waitp(lmb, ph);
        if (p) par1 ^= 1; else par0 ^= 1;
        if (t == 0) mbar_arm(lmb, 6144u);
      }
      // assemble dxdt = own + 3 remote + b2; dot; RK advance
      {
        const float* pb = sm + oPb + (p << 11);
        ull kacc = kpart;
#pragma unroll
        for (int r = 0; r < 4; ++r) {
          if (r != (int)rank)
            kacc = f2add(kacc, *(const ull*)(pb + 2 * (((r << 1) + pr) * 128 + c2)));
        }
        kacc = f2add(kacc, b2p);
        acc_dot = f2fma(f2mul(xs, kacc), pk(coef), acc_dot);
        ull acc;
        switch (stage) {
          case 0:
            ks0 = kacc;
            acc = f2mul(pk(0.2f), ks0);
            xs = f2fma(pk(dt), acc, y);
            break;
          case 1:
            ks1 = kacc;
            acc = f2mul(pk(0.075f), ks0);
            acc = f2fma(pk(0.225f), ks1, acc);
            xs = f2fma(pk(dt), acc, y);
            break;
          case 2:
            ks2 = kacc;
            acc = f2mul(pk((float)(44.0 / 45.0)), ks0);
            acc = f2fma(pk((float)(-56.0 / 15.0)), ks1, acc);
            acc = f2fma(pk((float)(32.0 / 9.0)), ks2, acc);
            xs = f2fma(pk(dt), acc, y);
            break;
          case 3:
            ks3 = kacc;
            acc = f2mul(pk((float)(19372.0 / 6561.0)), ks0);
            acc = f2fma(pk((float)(-25360.0 / 2187.0)), ks1, acc);
            acc = f2fma(pk((float)(64448.0 / 6561.0)), ks2, acc);
            acc = f2fma(pk((float)(-212.0 / 729.0)), ks3, acc);
            xs = f2fma(pk(dt), acc, y);
            break;
          case 4:
            ks4 = kacc;
            acc = f2mul(pk((float)(9017.0 / 3168.0)), ks0);
            acc = f2fma(pk((float)(-355.0 / 33.0)), ks1, acc);
            acc = f2fma(pk((float)(46732.0 / 5247.0)), ks2, acc);
            acc = f2fma(pk((float)(49.0 / 176.0)), ks3, acc);
            acc = f2fma(pk((float)(-5103.0 / 18656.0)), ks4, acc);
            xs = f2fma(pk(dt), acc, y);
            break;
          default:
            acc = f2mul(pk((float)(35.0 / 384.0)), ks0);
            acc = f2fma(pk((float)(500.0 / 1113.0)), ks2, acc);
            acc = f2fma(pk((float)(125.0 / 192.0)), ks3, acc);
            acc = f2fma(pk((float)(-2187.0 / 6784.0)), ks4, acc);
            acc = f2fma(pk((float)(11.0 / 84.0)), kacc, acc);
            y = f2fma(pk(dt), acc, y);
            xs = y;
            break;
        }
        sm[oXs + s0i * 128 + c2] = lo32(xs);
        sm[oXs + s1i * 128 + c2] = hi32(xs);
      }
    }
  }

  // ---- outputs: z ----
  out[(sb + s0i) * 128 + c2] = lo32(y);
  out[(sb + s1i) * 128 + c2] = hi32(y);

  // ---- final reductions ----
  {
    float t0 = wsum(lo32(tra)), t1 = wsum(hi32(tra));
    float t2 = wsum(lo32(trb)), t3 = wsum(hi32(trb));
    if (lane == 0) {
      sm[oScr + w * 4 + 0] = t0; sm[oScr + w * 4 + 1] = t1;
      sm[oScr + w * 4 + 2] = t2; sm[oScr + w * 4 + 3] = t3;
    }
  }
  {
    float d0 = wsum(lo32(acc_dot)), d1 = wsum(hi32(acc_dot));
    if (lane == 0) { sm[oScr + 32 + w * 2] = d0; sm[oScr + 32 + w * 2 + 1] = d1; }
  }
  __syncthreads();
  if (t < 4) {
    float T = 0.f;
#pragma unroll
    for (int q = 0; q < 8; ++q) T += sm[oScr + q * 4 + t];
    const int gg = t >> 1, sp = t & 1;
    float D = 0.f;
#pragma unroll
    for (int q = 0; q < 4; ++q) D += sm[oScr + 32 + ((4 * gg + q) << 1) + sp];
    sm[oTx + t] = T;
    sm[oScr + t] = D;  // reuse (post-sync, this thread's reads done)
  }
  csync();
  if (t < 4) {
    const uint32_t ta = smem_u32(&sm[oTx + t]);
    float T4 = 0.f;
#pragma unroll
    for (uint32_t r = 0; r < 4; ++r) T4 += ldcf(ta, r);
    out[B * 128 + sb + t]     = sm[oLp + t] - T4;       // log_px
    out[B * 128 + B + sb + t] = sm[oScr + t] - T4;      // kl
  }
  csync();  // keep smem alive until peers finish remote reads
}

extern "C" void kernel_launch(void* const* d_in, const int* in_sizes, int n_in,
                              void* d_out, int out_size) {
  const float* x0 = (const float*)d_in[0];
  const float* W1 = (const float*)d_in[1];
  const float* b1 = (const float*)d_in[2];
  const float* u1 = (const float*)d_in[3];
  const float* W2 = (const float*)d_in[4];
  const float* b2 = (const float*)d_in[5];
  const int*   ns = (const int*)d_in[6];
  float* out = (float*)d_out;
  int B = in_sizes[0] / 128;
  vino_kernel<<<B, 256>>>(x0, W1, b1, u1, W2, b2, ns, out, B);
}

// round 17
// speedup vs baseline: 1.1152x; 1.1152x over previous
#include <cuda_runtime.h>
#include <cstdint>

typedef unsigned long long ull;

__constant__ float cCC[6]  = {0.f, 0.2f, 0.3f, 0.8f, (float)(8.0/9.0), 1.0f};
__constant__ float cBWv[6] = {(float)(35.0/384.0), 0.f, (float)(500.0/1113.0),
                              (float)(125.0/192.0), (float)(-2187.0/6784.0),
                              (float)(11.0/84.0)};

// ---- smem layout (float offsets), ~44KB static ----
#define oXs  0        /* [s:4][128] = 512 */
#define oA   512      /* [s:4][64]  = 256 */
#define oHP  768      /* [kq:4][s:4][64] = 1024 */
#define oPb  1792     /* exchange [p:2][src:8][t:128][4f] = 8192 */
#define oStg 9984     /* staging  [p:2][t:128][4f] = 1024 */
#define oScr 11008    /* 32 */
#define oTx  11040    /* 4 */
#define oLp  11044    /* 4 */
#define SMF  11048

__device__ __forceinline__ ull pk(float w) {
  ull r; asm("mov.b64 %0, {%1, %2};" : "=l"(r) : "f"(w), "f"(w)); return r;
}
__device__ __forceinline__ ull mk2(float a, float b) {
  ull r; asm("mov.b64 %0, {%1, %2};" : "=l"(r) : "f"(a), "f"(b)); return r;
}
__device__ __forceinline__ float lo32(ull v) { return __uint_as_float((unsigned)v); }
__device__ __forceinline__ float hi32(ull v) { return __uint_as_float((unsigned)(v >> 32)); }
__device__ __forceinline__ ull f2fma(ull a, ull b, ull c) {
  ull d; asm("fma.rn.f32x2 %0,%1,%2,%3;" : "=l"(d) : "l"(a), "l"(b), "l"(c)); return d;
}
__device__ __forceinline__ ull f2add(ull a, ull b) {
  ull d; asm("add.rn.f32x2 %0,%1,%2;" : "=l"(d) : "l"(a), "l"(b)); return d;
}
__device__ __forceinline__ ull f2mul(ull a, ull b) {
  ull d; asm("mul.rn.f32x2 %0,%1,%2;" : "=l"(d) : "l"(a), "l"(b)); return d;
}
__device__ __forceinline__ float wsum(float v) {
#pragma unroll
  for (int o = 16; o > 0; o >>= 1) v += __shfl_xor_sync(0xffffffffu, v, o);
  return v;
}
__device__ __forceinline__ uint32_t smem_u32(const void* p) {
  uint32_t a;
  asm("{.reg .u64 t; cvta.to.shared.u64 t, %1; cvt.u32.u64 %0, t;}" : "=r"(a) : "l"(p));
  return a;
}
__device__ __forceinline__ uint32_t mapa_u32(uint32_t addr, uint32_t rank) {
  uint32_t ra; asm("mapa.shared::cluster.u32 %0, %1, %2;" : "=r"(ra) : "r"(addr), "r"(rank));
  return ra;
}
__device__ __forceinline__ float ldcf(uint32_t addr, uint32_t rank) {
  uint32_t ra = mapa_u32(addr, rank);
  float v; asm volatile("ld.shared::cluster.f32 %0, [%1];" : "=f"(v) : "r"(ra)); return v;
}
__device__ __forceinline__ void csync() {
  asm volatile("barrier.cluster.arrive.aligned;" ::: "memory");
  asm volatile("barrier.cluster.wait.aligned;" ::: "memory");
}
__device__ __forceinline__ void mbar_init(uint32_t mb, unsigned cnt) {
  asm volatile("mbarrier.init.shared::cta.b64 [%0], %1;" :: "r"(mb), "r"(cnt) : "memory");
}
__device__ __forceinline__ void mbar_arm(uint32_t mb, unsigned tx) {
  asm volatile("mbarrier.arrive.expect_tx.shared::cta.b64 _, [%0], %1;"
               :: "r"(mb), "r"(tx) : "memory");
}
__device__ __forceinline__ void bulk_copy512(uint32_t dst_cluster, uint32_t src_cta,
                                             uint32_t rmb_cluster) {
  asm volatile(
      "cp.async.bulk.shared::cluster.shared::cta.mbarrier::complete_tx::bytes "
      "[%0], [%1], 512, [%2];"
      :: "r"(dst_cluster), "r"(src_cta), "r"(rmb_cluster) : "memory");
}
__device__ __forceinline__ void waitp(uint32_t mb, unsigned ph) {
  unsigned done;
  asm volatile(
      "{\n\t.reg .pred p;\n\t"
      "mbarrier.try_wait.parity.acquire.cta.shared::cta.b64 p, [%1], %2;\n\t"
      "selp.u32 %0,1,0,p;\n\t}"
      : "=r"(done) : "r"(mb), "r"(ph) : "memory");
  while (!done) {
    asm volatile(
        "{\n\t.reg .pred p;\n\t"
        "mbarrier.try_wait.parity.acquire.cta.shared::cta.b64 p, [%1], %2, 0x989680;\n\t"
        "selp.u32 %0,1,0,p;\n\t}"
        : "=r"(done) : "r"(mb), "r"(ph) : "memory");
  }
}
__device__ __forceinline__ float ftanh(float x) {
  float e = __expf(2.f * x);
  return 1.f - __fdividef(2.f, e + 1.f);
}

__global__ void __launch_bounds__(128, 2) __cluster_dims__(8, 1, 1)
vino_kernel(const float* __restrict__ x0g, const float* __restrict__ W1g,
            const float* __restrict__ b1g, const float* __restrict__ u1g,
            const float* __restrict__ W2g, const float* __restrict__ b2g,
            const int* __restrict__ nsp, float* __restrict__ out, int B) {
  __shared__ __align__(16) float sm[SMF];
  __shared__ __align__(8) unsigned long long smbar[2];
  const int t = threadIdx.x;
  const int w = t >> 5, lane = t & 31;
  const int cq = t & 31, kq = t >> 5;   // G1: cols {cq, cq+32}, k in [32kq,+32)
  const int cc = t & 63, sh = t >> 6;   // tanh: col cc, samples {2sh, 2sh+1}
  const int c2 = t;                     // G2/RK: d-col c2 (0..127)
  uint32_t rank; asm("mov.u32 %0, %%cluster_ctarank;" : "=r"(rank));
  const int hbase = (int)rank << 6;     // 64 h-cols per CTA
  const int sb = (blockIdx.x >> 3) << 2;

  // ---- persistent weights ----
  // W1: cols {hbase+cq, hbase+cq+32}, k-pairs 32kq+2i, i = 0..15 (32 k/thread)
  ull w1p[2][16];
#pragma unroll
  for (int j = 0; j < 2; ++j)
#pragma unroll
    for (int i = 0; i < 16; ++i) {
      const int k0 = (kq << 5) + 2 * i;
      const int col = hbase + cq + 32 * j;
      w1p[j][i] = mk2(W1g[k0 * 512 + col], W1g[(k0 + 1) * 512 + col]);
    }
  // W2: col c2, local h-pairs (hbase+2i, +1), i = 0..31
  ull w2p[32];
#pragma unroll
  for (int i = 0; i < 32; ++i) {
    const int h0 = hbase + 2 * i;
    w2p[i] = mk2(W2g[h0 * 128 + c2], W2g[(h0 + 1) * 128 + c2]);
  }

  // ---- per-thread constants ----
  const float b1r = b1g[hbase + cc];
  const float u1r = u1g[hbase + cc];
  const ull b2p = pk(b2g[c2]);
  float mr = 0.f;
#pragma unroll 4
  for (int i = 0; i < 128; ++i)
    mr = fmaf(W1g[i * 512 + hbase + cc], W2g[(hbase + cc) * 128 + i], mr);

  // ---- state: (s0,s1) and (s2,s3) pairs at d-col c2 ----
  ull y01 = mk2(x0g[(sb + 0) * 128 + c2], x0g[(sb + 1) * 128 + c2]);
  ull y23 = mk2(x0g[(sb + 2) * 128 + c2], x0g[(sb + 3) * 128 + c2]);
  ull xs01 = y01, xs23 = y23;
  sm[oXs + 0 * 128 + c2] = lo32(xs01);
  sm[oXs + 1 * 128 + c2] = hi32(xs01);
  sm[oXs + 2 * 128 + c2] = lo32(xs23);
  sm[oXs + 3 * 128 + c2] = hi32(xs23);

  // ---- mbarriers + bulk-copy addresses ----
  const uint32_t mb0 = smem_u32(&smbar[0]);
  if (t == 0) {
    mbar_init(mb0, 1); mbar_init(mb0 + 8, 1);
    mbar_arm(mb0, 14336u); mbar_arm(mb0 + 8, 14336u);  // 7 peers x 2048B
  }
  const uint32_t stgb = smem_u32(sm + oStg);
  uint32_t dstb[7], rmbb[7];
  {
    // my warp chunk inside a peer's Pb: [src=rank][bytes w*512 .. +512)
    const uint32_t doff = smem_u32(sm + oPb) + ((uint32_t)rank << 11) + ((uint32_t)w << 9);
    int j = 0;
#pragma unroll
    for (uint32_t r = 0; r < 8; ++r) {
      if (r != rank) {
        dstb[j] = mapa_u32(doff, r);
        rmbb[j] = mapa_u32(mb0, r);
        ++j;
      }
    }
  }

  // ---- log p(x0) (local; identical in all ranks) ----
  {
    float s0 = wsum(lo32(y01) * lo32(y01)), s1 = wsum(hi32(y01) * hi32(y01));
    float s2 = wsum(lo32(y23) * lo32(y23)), s3 = wsum(hi32(y23) * hi32(y23));
    if (lane == 0) {
      sm[oScr + w * 4 + 0] = s0; sm[oScr + w * 4 + 1] = s1;
      sm[oScr + w * 4 + 2] = s2; sm[oScr + w * 4 + 3] = s3;
    }
  }
  __syncthreads();
  if (t < 4) {
    float ss = 0.f;
#pragma unroll
    for (int q = 0; q < 4; ++q) ss += sm[oScr + q * 4 + t];
    sm[oLp + t] = -0.5f * ss - 117.6241322501981f;  // 64*log(2*pi)
  }
  csync();  // mbar arming + smem init visible cluster-wide

  const int ns = *nsp;
  const float dt = 1.0f / (float)ns;
  ull k0a = 0, k0b = 0, k1a = 0, k1b = 0, k2a = 0, k2b = 0;
  ull k3a = 0, k3b = 0, k4a = 0, k4b = 0;
  ull tra = 0;                 // trace pair for samples {2sh, 2sh+1}
  ull dot01 = 0, dot23 = 0;
  unsigned par0 = 0, par1 = 0;

  for (int step = 0; step < ns; ++step) {
    const float tstep = (float)step * dt;
#pragma unroll 1
    for (int stage = 0; stage < 6; ++stage) {
      const float coef = dt * cBWv[stage];
      const float tcur = tstep + cCC[stage] * dt;
      const int p = stage & 1;

      __syncthreads();                       // S_A: xs visible
      // ---- G1: 2 cols x 32 k x 4 samples ----
      {
        const float* xb = sm + oXs + (kq << 5);
        ull a00 = 0, a01 = 0, a02 = 0, a03 = 0;   // col j=0
        ull a10 = 0, a11 = 0, a12 = 0, a13 = 0;   // col j=1
#pragma unroll
        for (int i = 0; i < 8; ++i) {
          ulonglong2 x0 = *(const ulonglong2*)(xb + 0 * 128 + (i << 2));
          ulonglong2 x1 = *(const ulonglong2*)(xb + 1 * 128 + (i << 2));
          ulonglong2 x2 = *(const ulonglong2*)(xb + 2 * 128 + (i << 2));
          ulonglong2 x3 = *(const ulonglong2*)(xb + 3 * 128 + (i << 2));
          ull w0a = w1p[0][2 * i], w0b = w1p[0][2 * i + 1];
          ull w1a = w1p[1][2 * i], w1b = w1p[1][2 * i + 1];
          a00 = f2fma(w0a, x0.x, a00); a00 = f2fma(w0b, x0.y, a00);
          a01 = f2fma(w0a, x1.x, a01); a01 = f2fma(w0b, x1.y, a01);
          a02 = f2fma(w0a, x2.x, a02); a02 = f2fma(w0b, x2.y, a02);
          a03 = f2fma(w0a, x3.x, a03); a03 = f2fma(w0b, x3.y, a03);
          a10 = f2fma(w1a, x0.x, a10); a10 = f2fma(w1b, x0.y, a10);
          a11 = f2fma(w1a, x1.x, a11); a11 = f2fma(w1b, x1.y, a11);
          a12 = f2fma(w1a, x2.x, a12); a12 = f2fma(w1b, x2.y, a12);
          a13 = f2fma(w1a, x3.x, a13); a13 = f2fma(w1b, x3.y, a13);
        }
        float* d0 = sm + oHP + (kq << 8) + cq;
        d0[0 * 64]      = lo32(a00) + hi32(a00);
        d0[1 * 64]      = lo32(a01) + hi32(a01);
        d0[2 * 64]      = lo32(a02) + hi32(a02);
        d0[3 * 64]      = lo32(a03) + hi32(a03);
        d0[0 * 64 + 32] = lo32(a10) + hi32(a10);
        d0[1 * 64 + 32] = lo32(a11) + hi32(a11);
        d0[2 * 64 + 32] = lo32(a12) + hi32(a12);
        d0[3 * 64 + 32] = lo32(a13) + hi32(a13);
      }
      __syncthreads();                       // S_B: HP visible

      // ---- tanh + trace: col cc, samples {2sh, 2sh+1} ----
      {
        const float bias = fmaf(tcur, u1r, b1r);
        const int sA = 2 * sh, sB = 2 * sh + 1;
        float hA = bias, hB = bias;
#pragma unroll
        for (int q = 0; q < 4; ++q) {
          hA += sm[oHP + (q << 8) + sA * 64 + cc];
          hB += sm[oHP + (q << 8) + sB * 64 + cc];
        }
        float aA = ftanh(hA), aB = ftanh(hB);
        sm[oA + sA * 64 + cc] = aA;
        sm[oA + sB * 64 + cc] = aB;
        tra = f2fma(mk2((1.f - aA * aA) * mr, (1.f - aB * aB) * mr),
                    pk(coef), tra);
      }
      __syncthreads();                       // S_C: a visible

      // ---- G2: d-col c2, full local K=64, 4 samples (registers) ----
      ull kp01, kp23;
      {
        const float* ab = sm + oA;
        ull g0 = 0, g1 = 0, g2 = 0, g3 = 0;
#pragma unroll
        for (int i = 0; i < 16; ++i) {
          ulonglong2 a0 = *(const ulonglong2*)(ab + 0 * 64 + (i << 2));
          ulonglong2 a1 = *(const ulonglong2*)(ab + 1 * 64 + (i << 2));
          ulonglong2 a2 = *(const ulonglong2*)(ab + 2 * 64 + (i << 2));
          ulonglong2 a3 = *(const ulonglong2*)(ab + 3 * 64 + (i << 2));
          ull wa = w2p[2 * i], wb = w2p[2 * i + 1];
          g0 = f2fma(wa, a0.x, g0); g0 = f2fma(wb, a0.y, g0);
          g1 = f2fma(wa, a1.x, g1); g1 = f2fma(wb, a1.y, g1);
          g2 = f2fma(wa, a2.x, g2); g2 = f2fma(wb, a2.y, g2);
          g3 = f2fma(wa, a3.x, g3); g3 = f2fma(wb, a3.y, g3);
        }
        kp01 = mk2(lo32(g0) + hi32(g0), lo32(g1) + hi32(g1));
        kp23 = mk2(lo32(g2) + hi32(g2), lo32(g3) + hi32(g3));
      }

      // ---- stage into parity staging; lane 0 bulk-pushes warp's 512B ----
      {
        ull* stg = (ull*)(sm + oStg + (p << 9));
        stg[2 * t]     = kp01;
        stg[2 * t + 1] = kp23;
        __syncwarp();
        if (lane == 0) {
          asm volatile("fence.proxy.async.shared::cta;" ::: "memory");
          const uint32_t src = stgb + ((uint32_t)p << 11) + ((uint32_t)w << 9);
          const uint32_t dof = (uint32_t)p << 14;   // p * 16384 B
          const uint32_t mof = (uint32_t)p << 3;
#pragma unroll
          for (int r = 0; r < 7; ++r)
            bulk_copy512(dstb[r] + dof, src, rmbb[r] + mof);
        }
      }

      // ---- wait for 14336B from 7 peers, re-arm ----
      {
        const uint32_t lmb = mb0 + (p << 3);
        unsigned ph = p ? par1 : par0;
        waitp(lmb, ph);
        if (p) par1 ^= 1; else par0 ^= 1;
        if (t == 0) mbar_arm(lmb, 14336u);
      }

      // ---- assemble dxdt = own + 7 peers + b2; dot; RK advance ----
      {
        const float* pbb = sm + oPb + (p << 12);
        ull kacc01 = kp01, kacc23 = kp23;
#pragma unroll
        for (int r = 0; r < 8; ++r) {
          if (r != (int)rank) {
            const float* pr_ = pbb + (r << 9) + (t << 2);
            kacc01 = f2add(kacc01, *(const ull*)pr_);
            kacc23 = f2add(kacc23, *(const ull*)(pr_ + 2));
          }
        }
        kacc01 = f2add(kacc01, b2p);
        kacc23 = f2add(kacc23, b2p);
        dot01 = f2fma(f2mul(xs01, kacc01), pk(coef), dot01);
        dot23 = f2fma(f2mul(xs23, kacc23), pk(coef), dot23);
        ull aA, aB;
        switch (stage) {
          case 0:
            k0a = kacc01; k0b = kacc23;
            aA = f2mul(pk(0.2f), k0a); aB = f2mul(pk(0.2f), k0b);
            break;
          case 1:
            k1a = kacc01; k1b = kacc23;
            aA = f2fma(pk(0.225f), k1a, f2mul(pk(0.075f), k0a));
            aB = f2fma(pk(0.225f), k1b, f2mul(pk(0.075f), k0b));
            break;
          case 2:
            k2a = kacc01; k2b = kacc23;
            aA = f2mul(pk((float)(44.0 / 45.0)), k0a);
            aA = f2fma(pk((float)(-56.0 / 15.0)), k1a, aA);
            aA = f2fma(pk((float)(32.0 / 9.0)), k2a, aA);
            aB = f2mul(pk((float)(44.0 / 45.0)), k0b);
            aB = f2fma(pk((float)(-56.0 / 15.0)), k1b, aB);
            aB = f2fma(pk((float)(32.0 / 9.0)), k2b, aB);
            break;
          case 3:
            k3a = kacc01; k3b = kacc23;
            aA = f2mul(pk((float)(19372.0 / 6561.0)), k0a);
            aA = f2fma(pk((float)(-25360.0 / 2187.0)), k1a, aA);
            aA = f2fma(pk((float)(64448.0 / 6561.0)), k2a, aA);
            aA = f2fma(pk((float)(-212.0 / 729.0)), k3a, aA);
            aB = f2mul(pk((float)(19372.0 / 6561.0)), k0b);
            aB = f2fma(pk((float)(-25360.0 / 2187.0)), k1b, aB);
            aB = f2fma(pk((float)(64448.0 / 6561.0)), k2b, aB);
            aB = f2fma(pk((float)(-212.0 / 729.0)), k3b, aB);
            break;
          case 4:
            k4a = kacc01; k4b = kacc23;
            aA = f2mul(pk((float)(9017.0 / 3168.0)), k0a);
            aA = f2fma(pk((float)(-355.0 / 33.0)), k1a, aA);
            aA = f2fma(pk((float)(46732.0 / 5247.0)), k2a, aA);
            aA = f2fma(pk((float)(49.0 / 176.0)), k3a, aA);
            aA = f2fma(pk((float)(-5103.0 / 18656.0)), k4a, aA);
            aB = f2mul(pk((float)(9017.0 / 3168.0)), k0b);
            aB = f2fma(pk((float)(-355.0 / 33.0)), k1b, aB);
            aB = f2fma(pk((float)(46732.0 / 5247.0)), k2b, aB);
            aB = f2fma(pk((float)(49.0 / 176.0)), k3b, aB);
            aB = f2fma(pk((float)(-5103.0 / 18656.0)), k4b, aB);
            break;
          default:
            aA = f2mul(pk((float)(35.0 / 384.0)), k0a);
            aA = f2fma(pk((float)(500.0 / 1113.0)), k2a, aA);
            aA = f2fma(pk((float)(125.0 / 192.0)), k3a, aA);
            aA = f2fma(pk((float)(-2187.0 / 6784.0)), k4a, aA);
            aA = f2fma(pk((float)(11.0 / 84.0)), kacc01, aA);
            aB = f2mul(pk((float)(35.0 / 384.0)), k0b);
            aB = f2fma(pk((float)(500.0 / 1113.0)), k2b, aB);
            aB = f2fma(pk((float)(125.0 / 192.0)), k3b, aB);
            aB = f2fma(pk((float)(-2187.0 / 6784.0)), k4b, aB);
            aB = f2fma(pk((float)(11.0 / 84.0)), kacc23, aB);
            break;
        }
        if (stage == 5) {
          y01 = f2fma(pk(dt), aA, y01); xs01 = y01;
          y23 = f2fma(pk(dt), aB, y23); xs23 = y23;
        } else {
          xs01 = f2fma(pk(dt), aA, y01);
          xs23 = f2fma(pk(dt), aB, y23);
        }
        sm[oXs + 0 * 128 + c2] = lo32(xs01);
        sm[oXs + 1 * 128 + c2] = hi32(xs01);
        sm[oXs + 2 * 128 + c2] = lo32(xs23);
        sm[oXs + 3 * 128 + c2] = hi32(xs23);
      }
    }
  }

  // ---- outputs: z (identical in all ranks; rank 0 writes) ----
  if (rank == 0) {
    out[(sb + 0) * 128 + c2] = lo32(y01);
    out[(sb + 1) * 128 + c2] = hi32(y01);
    out[(sb + 2) * 128 + c2] = lo32(y23);
    out[(sb + 3) * 128 + c2] = hi32(y23);
  }

  // ---- final reductions ----
  // trace: warp w covers samples {2(w>>1), 2(w>>1)+1}; cross-rank sum needed
  {
    float tl = wsum(lo32(tra)), th = wsum(hi32(tra));
    if (lane == 0) { sm[oScr + w * 2] = tl; sm[oScr + w * 2 + 1] = th; }
  }
  // dot: local (full d in every rank)
  {
    float d0 = wsum(lo32(dot01)), d1 = wsum(hi32(dot01));
    float d2 = wsum(lo32(dot23)), d3 = wsum(hi32(dot23));
    if (lane == 0) {
      sm[oScr + 16 + w * 4 + 0] = d0; sm[oScr + 16 + w * 4 + 1] = d1;
      sm[oScr + 16 + w * 4 + 2] = d2; sm[oScr + 16 + w * 4 + 3] = d3;
    }
  }
  __syncthreads();
  if (t < 4) {
    const int shh = t >> 1, sp = t & 1;
    float T = sm[oScr + (2 * shh) * 2 + sp] + sm[oScr + (2 * shh + 1) * 2 + sp];
    float D = 0.f;
#pragma unroll
    for (int q = 0; q < 4; ++q) D += sm[oScr + 16 + q * 4 + t];
    sm[oTx + t] = T;
    sm[oScr + t] = D;  // reuse scratch (this thread's reads done)
  }
  csync();
  if (rank == 0 && t < 4) {
    const uint32_t ta = smem_u32(&sm[oTx + t]);
    float T8 = 0.f;
#pragma unroll
    for (uint32_t r = 0; r < 8; ++r) T8 += ldcf(ta, r);
    out[B * 128 + sb + t]     = sm[oLp + t] - T8;   // log_px
    out[B * 128 + B + sb + t] = sm[oScr + t] - T8;  // kl
  }
  csync();  // keep smem alive until peers finish remote reads
}

extern "C" void kernel_launch(void* const* d_in, const int* in_sizes, int n_in,
                              void* d_out, int out_size) {
  const float* x0 = (const float*)d_in[0];
  const float* W1 = (const float*)d_in[1];
  const float* b1 = (const float*)d_in[2];
  const float* u1 = (const float*)d_in[3];
  const float* W2 = (const float*)d_in[4];
  const float* b2 = (const float*)d_in[5];
  const int*   ns = (const int*)d_in[6];
  float* out = (float*)d_out;
  int B = in_sizes[0] / 128;
  vino_kernel<<<B * 2, 128>>>(x0, W1, b1, u1, W2, b2, ns, out, B);
}